// round 3
// baseline (speedup 1.0000x reference)
#include <cuda_runtime.h>
#include <math.h>

// Problem constants
#define BATCH 64
#define HW    56           // spatial side
#define SEQ   3136         // 56*56
#define EMB   96
#define HEADS 3
#define EH    32           // head dim
#define WS    7
#define WS2   49
#define NWIN  64           // 8*8 windows
#define N3E   288          // 3*EMB

#define SCALE 0.17677669529663687f  // 1/sqrt(32)

// Scratch buffers (device globals — no runtime allocation allowed)
__device__ float g_Q[BATCH * HEADS * NWIN * WS2 * EH];
__device__ float g_K[BATCH * HEADS * NWIN * WS2 * EH];
__device__ float g_V[BATCH * HEADS * NWIN * WS2 * EH];
__device__ float g_O[BATCH * SEQ * EMB];

// ---------------------------------------------------------------------------
// Kernel 1: qkv = x @ w1^T + b1, fused with roll(-4,-4) + window partition.
// Tile: 64 rows x 96 cols, K=96. Block 256 threads, 4x6 micro-tile per thread.
// Epilogue scatters into g_Q/g_K/g_V in [b,H,win,49,32] layout.
// ---------------------------------------------------------------------------
__global__ __launch_bounds__(256) void k_qkv(const float* __restrict__ x,
                                             const float* __restrict__ w1,
                                             const float* __restrict__ b1) {
    __shared__ float xs[64][97];
    __shared__ float ws[96][97];
    const int rowTile = blockIdx.x;   // 0..3135
    const int colTile = blockIdx.y;   // 0..2
    const int t = threadIdx.x;
    const int row0 = rowTile * 64;
    const int c0 = colTile * 96;

    // Load x tile [64 x 96]
    #pragma unroll
    for (int i = t; i < 64 * 96; i += 256) {
        int r = i / 96, kk = i % 96;
        xs[r][kk] = x[(row0 + r) * 96 + kk];
    }
    // Load w1 tile transposed: ws[k][j] = w1[c0+j][k]
    #pragma unroll
    for (int i = t; i < 96 * 96; i += 256) {
        int j = i / 96, kk = i % 96;
        ws[kk][j] = w1[(c0 + j) * 96 + kk];
    }
    __syncthreads();

    const int ty = t >> 4;   // 0..15 -> rows
    const int tx = t & 15;   // 0..15 -> cols
    float acc[4][6];
    #pragma unroll
    for (int i = 0; i < 4; i++)
        #pragma unroll
        for (int j = 0; j < 6; j++) acc[i][j] = 0.f;

    #pragma unroll 4
    for (int kk = 0; kk < 96; ++kk) {
        float a[4], bb[6];
        #pragma unroll
        for (int i = 0; i < 4; i++) a[i] = xs[ty * 4 + i][kk];
        #pragma unroll
        for (int j = 0; j < 6; j++) bb[j] = ws[kk][tx * 6 + j];
        #pragma unroll
        for (int i = 0; i < 4; i++)
            #pragma unroll
            for (int j = 0; j < 6; j++) acc[i][j] += a[i] * bb[j];
    }

    // Epilogue: add bias, scatter into windowed Q/K/V
    #pragma unroll
    for (int i = 0; i < 4; i++) {
        const int row = row0 + ty * 4 + i;
        const int b   = row / SEQ;
        const int s   = row % SEQ;
        const int y   = s / HW;
        const int xx  = s % HW;
        // rolled coords: rolled[yr] = orig[(yr+4)%56] -> yr = (y-4)%56
        const int yr = (y + HW - 4) % HW;
        const int xr = (xx + HW - 4) % HW;
        const int wh = yr / WS, m1 = yr % WS;
        const int ww = xr / WS, m2 = xr % WS;
        const int win = wh * 8 + ww;
        const int m = m1 * WS + m2;
        #pragma unroll
        for (int j = 0; j < 6; j++) {
            const int col = c0 + tx * 6 + j;   // 0..287
            const float v = acc[i][j] + __ldg(&b1[col]);
            const int k = col % 3;
            const int e = col / 3;
            const int head = e >> 5;
            const int eh = e & 31;
            const int dst = (((b * HEADS + head) * NWIN + win) * WS2 + m) * EH + eh;
            if (k == 0)      g_Q[dst] = v;
            else if (k == 1) g_K[dst] = v;
            else             g_V[dst] = v;
        }
    }
}

// ---------------------------------------------------------------------------
// Kernel 2: window attention. One block per (b, head, window), 256 threads.
// Epilogue writes O already un-windowed + inverse-rolled into dense [b,s,96].
// ---------------------------------------------------------------------------
__global__ __launch_bounds__(256) void k_attn() {
    __shared__ float Qs[WS2][33];
    __shared__ float Ks[WS2][33];
    __shared__ float Vs[WS2][33];
    __shared__ float Ss[WS2][50];

    const int blk = blockIdx.x;
    const int win = blk & 63;
    const int head = (blk >> 6) % 3;
    const int b = blk / (NWIN * HEADS);
    const int base = ((b * HEADS + head) * NWIN + win) * WS2 * EH;
    const int t = threadIdx.x;

    for (int i = t; i < WS2 * EH; i += 256) {
        const int m = i >> 5, kk = i & 31;
        Qs[m][kk] = g_Q[base + i];
        Ks[m][kk] = g_K[base + i];
        Vs[m][kk] = g_V[base + i];
    }
    __syncthreads();

    const int wh = win >> 3, ww = win & 7;
    const bool lastRow = (wh == 7);
    const bool lastCol = (ww == 7);

    // Scores + masks
    for (int idx = t; idx < WS2 * WS2; idx += 256) {
        const int m = idx / WS2, n = idx % WS2;
        float acc = 0.f;
        #pragma unroll
        for (int kk = 0; kk < EH; kk++) acc += Qs[m][kk] * Ks[n][kk];
        acc *= SCALE;
        bool msk = (lastRow && ((m / 7 >= 4) != (n / 7 >= 4))) ||
                   (lastCol && ((m % 7 >= 4) != (n % 7 >= 4)));
        Ss[m][n] = msk ? -1e30f : acc;
    }
    __syncthreads();

    // Softmax: one warp per row
    const int warp = t >> 5, lane = t & 31;
    for (int m = warp; m < WS2; m += 8) {
        float v0 = (lane < WS2) ? Ss[m][lane] : -1e30f;
        float v1 = (lane + 32 < WS2) ? Ss[m][lane + 32] : -1e30f;
        float mx = fmaxf(v0, v1);
        #pragma unroll
        for (int off = 16; off > 0; off >>= 1)
            mx = fmaxf(mx, __shfl_xor_sync(0xffffffff, mx, off));
        float e0 = (lane < WS2) ? __expf(v0 - mx) : 0.f;
        float e1 = (lane + 32 < WS2) ? __expf(v1 - mx) : 0.f;
        float sm = e0 + e1;
        #pragma unroll
        for (int off = 16; off > 0; off >>= 1)
            sm += __shfl_xor_sync(0xffffffff, sm, off);
        const float inv = __frcp_rn(sm);
        if (lane < WS2) Ss[m][lane] = e0 * inv;
        if (lane + 32 < WS2) Ss[m][lane + 32] = e1 * inv;
    }
    __syncthreads();

    // O = att @ V, scatter to dense layout with inverse roll(+3)
    for (int idx = t; idx < WS2 * EH; idx += 256) {
        const int m = idx >> 5, eh = idx & 31;
        float acc = 0.f;
        #pragma unroll
        for (int n = 0; n < WS2; n++) acc += Ss[m][n] * Vs[n][eh];
        const int m1 = m / 7, m2 = m % 7;
        const int y = (wh * WS + m1 + 3) % HW;
        const int xx = (ww * WS + m2 + 3) % HW;
        g_O[(b * SEQ + y * HW + xx) * EMB + head * EH + eh] = acc;
    }
}

// ---------------------------------------------------------------------------
// Kernel 3: out = O @ w2^T + b2.  Tile 64 rows x 96 cols, K=96.
// ---------------------------------------------------------------------------
__global__ __launch_bounds__(256) void k_proj(const float* __restrict__ w2,
                                              const float* __restrict__ b2,
                                              float* __restrict__ out) {
    __shared__ float os[64][97];
    __shared__ float ws[96][97];
    const int row0 = blockIdx.x * 64;
    const int t = threadIdx.x;

    #pragma unroll
    for (int i = t; i < 64 * 96; i += 256) {
        int r = i / 96, kk = i % 96;
        os[r][kk] = g_O[(row0 + r) * 96 + kk];
    }
    #pragma unroll
    for (int i = t; i < 96 * 96; i += 256) {
        int j = i / 96, kk = i % 96;
        ws[kk][j] = w2[j * 96 + kk];
    }
    __syncthreads();

    const int ty = t >> 4;
    const int tx = t & 15;
    float acc[4][6];
    #pragma unroll
    for (int i = 0; i < 4; i++)
        #pragma unroll
        for (int j = 0; j < 6; j++) acc[i][j] = 0.f;

    #pragma unroll 4
    for (int kk = 0; kk < 96; ++kk) {
        float a[4], bb[6];
        #pragma unroll
        for (int i = 0; i < 4; i++) a[i] = os[ty * 4 + i][kk];
        #pragma unroll
        for (int j = 0; j < 6; j++) bb[j] = ws[kk][tx * 6 + j];
        #pragma unroll
        for (int i = 0; i < 4; i++)
            #pragma unroll
            for (int j = 0; j < 6; j++) acc[i][j] += a[i] * bb[j];
    }

    #pragma unroll
    for (int i = 0; i < 4; i++) {
        const int row = row0 + ty * 4 + i;
        #pragma unroll
        for (int j = 0; j < 6; j++) {
            const int col = tx * 6 + j;
            out[row * 96 + col] = acc[i][j] + __ldg(&b2[col]);
        }
    }
}

// ---------------------------------------------------------------------------
extern "C" void kernel_launch(void* const* d_in, const int* in_sizes, int n_in,
                              void* d_out, int out_size) {
    const float* x  = (const float*)d_in[0];
    const float* w1 = (const float*)d_in[1];
    const float* b1 = (const float*)d_in[2];
    const float* w2 = (const float*)d_in[3];
    const float* b2 = (const float*)d_in[4];
    float* out = (float*)d_out;

    // K1: QKV projection + roll + window scatter
    dim3 g1(SEQ * BATCH / 64, 3);
    k_qkv<<<g1, 256>>>(x, w1, b1);

    // K2: window attention (one block per b*head*window)
    k_attn<<<BATCH * HEADS * NWIN, 256>>>();

    // K3: output projection
    k_proj<<<SEQ * BATCH / 64, 256>>>(w2, b2, out);
}